// round 2
// baseline (speedup 1.0000x reference)
#include <cuda_runtime.h>
#include <math.h>

#define BB 64
#define TT 2048
#define II 256
#define HH 512
#define G3 1536          // 3*H

#define GRID_R 128       // persistent recurrent grid (<= 148 SMs -> co-resident)
#define BLK_R  128       // 4 warps: warp = one hidden column j'

// ---------------- scratch (static device allocations only) ----------------
__device__ float g_ig[(size_t)TT * G3 * BB];   // [t][gate_col j][b], bias folded in
__device__ float g_h[2][HH * BB];              // hT[k][b], double buffered
__device__ unsigned g_arrive;
__device__ volatile unsigned g_epoch;

// ---------------- helpers ----------------
__device__ __forceinline__ unsigned long long fma2(unsigned long long a,
                                                   unsigned long long b,
                                                   unsigned long long c) {
    unsigned long long d;
    asm("fma.rn.f32x2 %0, %1, %2, %3;" : "=l"(d) : "l"(a), "l"(b), "l"(c));
    return d;
}
__device__ __forceinline__ float2 u2f2(unsigned long long v) {
    float2 f;
    f.x = __uint_as_float((unsigned)(v & 0xffffffffull));
    f.y = __uint_as_float((unsigned)(v >> 32));
    return f;
}
__device__ __forceinline__ float sigmoidf_(float x) {
    return 1.0f / (1.0f + expf(-x));
}

// ---------------- reset: counters + h0 = 0 (graph-replay determinism) ----------------
__global__ void reset_kernel() {
    int idx = blockIdx.x * blockDim.x + threadIdx.x;
    if (idx == 0) { g_arrive = 0; g_epoch = 0; }
    for (int i = idx; i < HH * BB; i += gridDim.x * blockDim.x)
        g_h[0][i] = 0.0f;
}

// ---------------- phase 1: IG[t][j][b] = bias[j] + sum_i w_ih[j][i] * xs[b][t][i] ----------------
// grid: (T, 12). tile: 128 j x 64 b, K=256 in chunks of 64. 256 threads, 8x4 micro-tile.
__global__ void ig_kernel(const float* __restrict__ xs,
                          const float* __restrict__ w_ih,
                          const float* __restrict__ bias) {
    __shared__ float Ws[64][128];   // [ik][j_local]  32 KB
    __shared__ float Xs[64][64];    // [ik][b]        16 KB

    const int t   = blockIdx.x;
    const int jb  = blockIdx.y * 128;
    const int tid = threadIdx.x;
    const int tx  = tid & 15;   // b quad: b = tx*4 .. +3
    const int ty  = tid >> 4;   // j oct:  j = ty*8 .. +7

    float acc[8][4];
#pragma unroll
    for (int i = 0; i < 8; i++)
#pragma unroll
        for (int j = 0; j < 4; j++) acc[i][j] = 0.0f;

    for (int kc = 0; kc < II; kc += 64) {
        {   // load W chunk: thread -> (row jj, half), 32 floats each
            int jj = tid >> 1, half = tid & 1;
            const float* src = w_ih + (size_t)(jb + jj) * II + kc + half * 32;
#pragma unroll
            for (int q = 0; q < 8; q++) {
                float4 v = *(const float4*)(src + q * 4);
                int ik = half * 32 + q * 4;
                Ws[ik + 0][jj] = v.x; Ws[ik + 1][jj] = v.y;
                Ws[ik + 2][jj] = v.z; Ws[ik + 3][jj] = v.w;
            }
        }
        {   // load X chunk: thread -> (b, quarter), 16 floats each
            int b = tid >> 2, q = tid & 3;
            const float* src = xs + ((size_t)b * TT + t) * II + kc + q * 16;
#pragma unroll
            for (int v = 0; v < 4; v++) {
                float4 x4 = *(const float4*)(src + v * 4);
                int ik = q * 16 + v * 4;
                Xs[ik + 0][b] = x4.x; Xs[ik + 1][b] = x4.y;
                Xs[ik + 2][b] = x4.z; Xs[ik + 3][b] = x4.w;
            }
        }
        __syncthreads();
#pragma unroll
        for (int ik = 0; ik < 64; ik++) {
            float4 a0 = *(const float4*)&Ws[ik][ty * 8];
            float4 a1 = *(const float4*)&Ws[ik][ty * 8 + 4];
            float4 xv = *(const float4*)&Xs[ik][tx * 4];
            float a[8] = {a0.x, a0.y, a0.z, a0.w, a1.x, a1.y, a1.z, a1.w};
            float x[4] = {xv.x, xv.y, xv.z, xv.w};
#pragma unroll
            for (int i = 0; i < 8; i++)
#pragma unroll
                for (int j = 0; j < 4; j++)
                    acc[i][j] = fmaf(a[i], x[j], acc[i][j]);
        }
        __syncthreads();
    }
#pragma unroll
    for (int i = 0; i < 8; i++) {
        int j = jb + ty * 8 + i;
        float bj = bias[j];
        float4 o = {acc[i][0] + bj, acc[i][1] + bj, acc[i][2] + bj, acc[i][3] + bj};
        *(float4*)&g_ig[((size_t)t * G3 + j) * BB + tx * 4] = o;
    }
}

// ---------------- phase 2: persistent recurrence ----------------
__global__ void __launch_bounds__(BLK_R, 1)
gru_kernel(const float* __restrict__ w_hh,
           const float* __restrict__ b_n,
           float* __restrict__ out) {
    __shared__ float sw[4][3][HH][2];   // duplicated weight pairs, 48 KB

    const int tid  = threadIdx.x;
    const int warp = tid >> 5;
    const int lane = tid & 31;
    const int jp   = blockIdx.x * 4 + warp;   // hidden column 0..511
    const int b0   = lane * 2;                // two batch rows per lane

    // stage w_hh rows for this CTA's 4 columns x 3 gates, value-duplicated
    for (int idx = tid; idx < 4 * 3 * HH; idx += BLK_R) {
        int w = idx / (3 * HH);
        int rem = idx - w * 3 * HH;
        int g = rem / HH;
        int k = rem - g * HH;
        float v = w_hh[(size_t)(g * HH + (blockIdx.x * 4 + w)) * HH + k];
        sw[w][g][k][0] = v;
        sw[w][g][k][1] = v;
    }
    const float bn = b_n[jp];
    __syncthreads();

    float2 hout = make_float2(0.0f, 0.0f);

    for (int t = 0; t < TT; t++) {
        const float* hcur  = g_h[t & 1];
        float*       hnext = g_h[(t + 1) & 1];

        // gate inputs for this (j', b0..b0+1); issued early, used after the dot loop
        const float* igb = g_ig + ((size_t)t * G3 + jp) * BB + b0;
        float2 igr  = __ldcg((const float2*)(igb));
        float2 igz  = __ldcg((const float2*)(igb + (size_t)HH * BB));
        float2 ign  = __ldcg((const float2*)(igb + (size_t)2 * HH * BB));
        float2 hold = __ldcg((const float2*)(hcur + jp * BB + b0));

        unsigned long long ar = 0ull, az = 0ull, an = 0ull;
#pragma unroll 4
        for (int k = 0; k < HH; k += 2) {
            unsigned long long h0 =
                __ldcg((const unsigned long long*)(hcur + (k + 0) * BB + b0));
            unsigned long long h1 =
                __ldcg((const unsigned long long*)(hcur + (k + 1) * BB + b0));
            ulonglong2 wr = *(const ulonglong2*)&sw[warp][0][k][0];
            ulonglong2 wz = *(const ulonglong2*)&sw[warp][1][k][0];
            ulonglong2 wn = *(const ulonglong2*)&sw[warp][2][k][0];
            ar = fma2(h0, wr.x, ar);
            az = fma2(h0, wz.x, az);
            an = fma2(h0, wn.x, an);
            ar = fma2(h1, wr.y, ar);
            az = fma2(h1, wz.y, az);
            an = fma2(h1, wn.y, an);
        }

        float2 ra = u2f2(ar), za = u2f2(az), na = u2f2(an);
        float r0 = sigmoidf_(igr.x + ra.x);
        float z0 = sigmoidf_(igz.x + za.x);
        float n0 = tanhf(ign.x + r0 * (na.x + bn));
        float r1 = sigmoidf_(igr.y + ra.y);
        float z1 = sigmoidf_(igz.y + za.y);
        float n1 = tanhf(ign.y + r1 * (na.y + bn));
        hout.x = n0 + z0 * (hold.x - n0);
        hout.y = n1 + z1 * (hold.y - n1);
        *(float2*)(hnext + jp * BB + b0) = hout;

        // software grid barrier (all 128 CTAs co-resident: grid <= SM count)
        __syncthreads();
        if (tid == 0) {
            __threadfence();
            unsigned a = atomicAdd(&g_arrive, 1u) + 1u;
            if (a == (unsigned)(t + 1) * GRID_R) {
                __threadfence();
                g_epoch = (unsigned)(t + 1);
            } else {
                while (g_epoch < (unsigned)(t + 1)) { }
            }
            __threadfence();
        }
        __syncthreads();
    }

    out[(b0 + 0) * HH + jp] = hout.x;
    out[(b0 + 1) * HH + jp] = hout.y;
}

// ---------------- launch ----------------
extern "C" void kernel_launch(void* const* d_in, const int* in_sizes, int n_in,
                              void* d_out, int out_size) {
    const float* xs   = (const float*)d_in[0];
    const float* w_ih = (const float*)d_in[1];
    const float* w_hh = (const float*)d_in[2];
    const float* bias = (const float*)d_in[3];
    const float* b_n  = (const float*)d_in[4];
    float* out = (float*)d_out;

    reset_kernel<<<64, 256>>>();

    dim3 g1(TT, G3 / 128);
    ig_kernel<<<g1, 256>>>(xs, w_ih, bias);

    gru_kernel<<<GRID_R, BLK_R>>>(w_hh, b_n, out);
}

// round 6
// speedup vs baseline: 1.1495x; 1.1495x over previous
#include <cuda_runtime.h>
#include <math.h>

#define BB 64
#define TT 2048
#define II 256
#define HH 512
#define G3 1536          // 3*H

#define GRID_R 128       // persistent recurrent grid (<= 148 SMs, occ 1 -> co-resident)
#define BLK_R  128       // 4 warps; warp w owns k-range [w*128, w*128+128)

// dynamic smem layout (floats):
//   [0, 32768)        sh_h[512][64]          h staged, 128 KB
//   [32768, 45056)    sw2[4][12][128] float2 duplicated weights, 48 KB
//   [45056, 48128)    sh_part[4][12][64]     partial sums, 12 KB
#define SMEM_F_H    0
#define SMEM_F_W    32768
#define SMEM_F_P    45056
#define SMEM_BYTES  (48128 * 4)

// ---------------- scratch ----------------
__device__ float g_ig[(size_t)TT * G3 * BB];   // [t][gate_col j][b], bias folded in
__device__ float g_h[2][HH * BB];              // h[k][b], double buffered
__device__ unsigned g_flags[GRID_R];

// ---------------- helpers ----------------
__device__ __forceinline__ unsigned long long fma2(unsigned long long a,
                                                   unsigned long long b,
                                                   unsigned long long c) {
    unsigned long long d;
    asm("fma.rn.f32x2 %0, %1, %2, %3;" : "=l"(d) : "l"(a), "l"(b), "l"(c));
    return d;
}
__device__ __forceinline__ float2 u2f2(unsigned long long v) {
    float2 f;
    f.x = __uint_as_float((unsigned)(v & 0xffffffffull));
    f.y = __uint_as_float((unsigned)(v >> 32));
    return f;
}
__device__ __forceinline__ float sigmoidf_(float x) {
    return 1.0f / (1.0f + expf(-x));
}
__device__ __forceinline__ void cp16(unsigned dst, const void* src) {
    asm volatile("cp.async.cg.shared.global [%0], [%1], 16;" :: "r"(dst), "l"(src));
}

// ---------------- reset ----------------
__global__ void reset_kernel() {
    int idx = blockIdx.x * blockDim.x + threadIdx.x;
    if (idx < GRID_R) g_flags[idx] = 0;
    for (int i = idx; i < HH * BB; i += gridDim.x * blockDim.x)
        g_h[0][i] = 0.0f;
}

// ---------------- phase 1: IG[t][j][b] = bias[j] + sum_i w_ih[j][i] * xs[b][t][i] ----------------
__global__ void ig_kernel(const float* __restrict__ xs,
                          const float* __restrict__ w_ih,
                          const float* __restrict__ bias) {
    __shared__ float Ws[64][128];
    __shared__ float Xs[64][64];

    const int t   = blockIdx.x;
    const int jb  = blockIdx.y * 128;
    const int tid = threadIdx.x;
    const int tx  = tid & 15;
    const int ty  = tid >> 4;

    float acc[8][4];
#pragma unroll
    for (int i = 0; i < 8; i++)
#pragma unroll
        for (int j = 0; j < 4; j++) acc[i][j] = 0.0f;

    for (int kc = 0; kc < II; kc += 64) {
        {
            int jj = tid >> 1, half = tid & 1;
            const float* src = w_ih + (size_t)(jb + jj) * II + kc + half * 32;
#pragma unroll
            for (int q = 0; q < 8; q++) {
                float4 v = *(const float4*)(src + q * 4);
                int ik = half * 32 + q * 4;
                Ws[ik + 0][jj] = v.x; Ws[ik + 1][jj] = v.y;
                Ws[ik + 2][jj] = v.z; Ws[ik + 3][jj] = v.w;
            }
        }
        {
            int b = tid >> 2, q = tid & 3;
            const float* src = xs + ((size_t)b * TT + t) * II + kc + q * 16;
#pragma unroll
            for (int v = 0; v < 4; v++) {
                float4 x4 = *(const float4*)(src + v * 4);
                int ik = q * 16 + v * 4;
                Xs[ik + 0][b] = x4.x; Xs[ik + 1][b] = x4.y;
                Xs[ik + 2][b] = x4.z; Xs[ik + 3][b] = x4.w;
            }
        }
        __syncthreads();
#pragma unroll
        for (int ik = 0; ik < 64; ik++) {
            float4 a0 = *(const float4*)&Ws[ik][ty * 8];
            float4 a1 = *(const float4*)&Ws[ik][ty * 8 + 4];
            float4 xv = *(const float4*)&Xs[ik][tx * 4];
            float a[8] = {a0.x, a0.y, a0.z, a0.w, a1.x, a1.y, a1.z, a1.w};
            float x[4] = {xv.x, xv.y, xv.z, xv.w};
#pragma unroll
            for (int i = 0; i < 8; i++)
#pragma unroll
                for (int j = 0; j < 4; j++)
                    acc[i][j] = fmaf(a[i], x[j], acc[i][j]);
        }
        __syncthreads();
    }
#pragma unroll
    for (int i = 0; i < 8; i++) {
        int j = jb + ty * 8 + i;
        float bj = bias[j];
        float4 o = {acc[i][0] + bj, acc[i][1] + bj, acc[i][2] + bj, acc[i][3] + bj};
        *(float4*)&g_ig[((size_t)t * G3 + j) * BB + tx * 4] = o;
    }
}

// ---------------- phase 2: persistent recurrence ----------------
__global__ void __launch_bounds__(BLK_R, 1)
gru_kernel(const float* __restrict__ w_hh,
           const float* __restrict__ b_n_p,
           float* __restrict__ out) {
    extern __shared__ __align__(16) float smf[];
    float*  sh_h  = smf + SMEM_F_H;                 // [512][64]
    float2* sw2   = (float2*)(smf + SMEM_F_W);      // [4][12][128] dup pairs (local k)
    float*  sh_pt = smf + SMEM_F_P;                 // [4][12][64]

    const int tid  = threadIdx.x;
    const int warp = tid >> 5;
    const int lane = tid & 31;
    const int b0   = lane * 2;
    const int jp4  = blockIdx.x * 4;                // 4 hidden columns per CTA

    unsigned sh_h_addr;
    asm("{ .reg .u64 t0; cvta.to.shared.u64 t0, %1; cvt.u32.u64 %0, t0; }"
        : "=r"(sh_h_addr) : "l"(sh_h));

    // stage weights once: sw2[w][gc][kl] = dup(w_hh[(g*H + jp4+jj)*H + w*128+kl]), gc=g*4+jj
    for (int idx = tid; idx < 4 * 12 * 128; idx += BLK_R) {
        int w   = idx / 1536;
        int rem = idx - w * 1536;
        int gc  = rem >> 7;
        int kl  = rem & 127;
        int g   = gc >> 2, jj = gc & 3;
        float v = w_hh[(size_t)(g * HH + jp4 + jj) * HH + w * 128 + kl];
        sw2[(w * 12 + gc) * 128 + kl] = make_float2(v, v);
    }

    // per-thread output assignment: o = tid, tid+128 -> (jj, b)
    int jjv[2], bv[2], jgv[2];
    float bnv[2];
#pragma unroll
    for (int oo = 0; oo < 2; oo++) {
        int o = tid + oo * 128;
        jjv[oo] = o >> 6;
        bv[oo]  = o & 63;
        jgv[oo] = jp4 + jjv[oo];
        bnv[oo] = b_n_p[jgv[oo]];
    }
    __syncthreads();

    for (int t = 0; t < TT; t++) {
        const float* hcur  = g_h[t & 1];
        float*       hnext = g_h[(t + 1) & 1];

        // early gate-input loads (DRAM latency hidden under the step)
        float igr[2], igz[2], ign[2];
#pragma unroll
        for (int oo = 0; oo < 2; oo++) {
            const float* p = g_ig + (size_t)t * G3 * BB;
            igr[oo] = p[(size_t)(0 * HH + jgv[oo]) * BB + bv[oo]];
            igz[oo] = p[(size_t)(1 * HH + jgv[oo]) * BB + bv[oo]];
            ign[oo] = p[(size_t)(2 * HH + jgv[oo]) * BB + bv[oo]];
        }

        // stage this warp's k-chunk (32 KB) in 4 sub-chunks of 8 KB
        {
            const float4* src = (const float4*)hcur;
#pragma unroll
            for (int s = 0; s < 4; s++) {
                int base4 = (warp * 128 + s * 32) * 16;   // float4 index
#pragma unroll
                for (int i = 0; i < 16; i++) {
                    int idx = base4 + i * 32 + lane;
                    cp16(sh_h_addr + idx * 16, src + idx);
                }
                asm volatile("cp.async.commit_group;");
            }
        }

        unsigned long long acc[12];
#pragma unroll
        for (int gc = 0; gc < 12; gc++) acc[gc] = 0ull;

#pragma unroll 1
        for (int s = 0; s < 4; s++) {
            if (s == 0)      asm volatile("cp.async.wait_group 3;");
            else if (s == 1) asm volatile("cp.async.wait_group 2;");
            else if (s == 2) asm volatile("cp.async.wait_group 1;");
            else             asm volatile("cp.async.wait_group 0;");
            const int kb = warp * 128 + s * 32;
#pragma unroll 2
            for (int kk = 0; kk < 32; kk += 4) {
                const int k  = kb + kk;        // global k (h rows)
                const int kl = s * 32 + kk;    // local k (this warp's weight region)
                const unsigned long long* hrow = (const unsigned long long*)sh_h;
                unsigned long long h0 = hrow[(k + 0) * 32 + lane];
                unsigned long long h1 = hrow[(k + 1) * 32 + lane];
                unsigned long long h2 = hrow[(k + 2) * 32 + lane];
                unsigned long long h3 = hrow[(k + 3) * 32 + lane];
#pragma unroll
                for (int gc = 0; gc < 12; gc++) {
                    const ulonglong2* wp =
                        (const ulonglong2*)&sw2[(warp * 12 + gc) * 128 + kl];
                    ulonglong2 wA = wp[0];   // dup(w[k]), dup(w[k+1])
                    ulonglong2 wB = wp[1];   // dup(w[k+2]), dup(w[k+3])
                    acc[gc] = fma2(h0, wA.x, acc[gc]);
                    acc[gc] = fma2(h1, wA.y, acc[gc]);
                    acc[gc] = fma2(h2, wB.x, acc[gc]);
                    acc[gc] = fma2(h3, wB.y, acc[gc]);
                }
            }
        }

        // publish partials
#pragma unroll
        for (int gc = 0; gc < 12; gc++)
            *(float2*)&sh_pt[(warp * 12 + gc) * 64 + b0] = u2f2(acc[gc]);
        __syncthreads();   // (A)

        // reduce + gates + h write
#pragma unroll
        for (int oo = 0; oo < 2; oo++) {
            const int jj = jjv[oo], b = bv[oo], jg = jgv[oo];
            float pr = 0.0f, pz = 0.0f, pn = 0.0f;
#pragma unroll
            for (int w = 0; w < 4; w++) {
                pr += sh_pt[(w * 12 + 0 * 4 + jj) * 64 + b];
                pz += sh_pt[(w * 12 + 1 * 4 + jj) * 64 + b];
                pn += sh_pt[(w * 12 + 2 * 4 + jj) * 64 + b];
            }
            float r    = sigmoidf_(igr[oo] + pr);
            float z    = sigmoidf_(igz[oo] + pz);
            float hold = sh_h[jg * 64 + b];
            float n    = tanhf(ign[oo] + r * (pn + bnv[oo]));
            float hnew = n + z * (hold - n);
            if (t == TT - 1) out[b * HH + jg] = hnew;
            else             hnext[jg * 64 + b] = hnew;
        }
        __syncthreads();   // (B) all h writes + smem reads done

        if (t < TT - 1) {
            if (tid == 0)
                asm volatile("st.release.gpu.u32 [%0], %1;"
                             :: "l"(g_flags + blockIdx.x), "r"(t + 1) : "memory");
            unsigned v;
            do {
                asm volatile("ld.acquire.gpu.u32 %0, [%1];"
                             : "=r"(v) : "l"(g_flags + tid) : "memory");
            } while (v < (unsigned)(t + 1));
            __syncthreads();   // (C) whole CTA gated on all 128 flags
        }
    }
}

// ---------------- launch ----------------
extern "C" void kernel_launch(void* const* d_in, const int* in_sizes, int n_in,
                              void* d_out, int out_size) {
    const float* xs   = (const float*)d_in[0];
    const float* w_ih = (const float*)d_in[1];
    const float* w_hh = (const float*)d_in[2];
    const float* bias = (const float*)d_in[3];
    const float* b_n  = (const float*)d_in[4];
    float* out = (float*)d_out;

    cudaFuncSetAttribute(gru_kernel,
                         cudaFuncAttributeMaxDynamicSharedMemorySize, SMEM_BYTES);

    reset_kernel<<<64, 256>>>();

    dim3 g1(TT, G3 / 128);
    ig_kernel<<<g1, 256>>>(xs, w_ih, bias);

    gru_kernel<<<GRID_R, BLK_R, SMEM_BYTES>>>(w_hh, b_n, out);
}

// round 7
// speedup vs baseline: 1.6455x; 1.4315x over previous
#include <cuda_runtime.h>
#include <math.h>

#define BB 64
#define TT 2048
#define II 256
#define HH 512
#define G3 1536          // 3*H

#define GRID_R 128       // persistent recurrent grid (<= 148 SMs, occ 1 -> co-resident)
#define BLK_R  256       // 8 warps (2/SMSP); warp w owns k-range [w*64, w*64+64)

// dynamic smem layout (floats):
//   [0, 32768)        sh_h[512][64]           h staged, 128 KB
//   [32768, 45056)    sw2[8][12][64] float2   duplicated weights, 48 KB
//   [45056, 51200)    sh_pt[8][12][64]        partial sums, 24 KB
#define SMEM_F_H    0
#define SMEM_F_W    32768
#define SMEM_F_P    45056
#define SMEM_BYTES  (51200 * 4)

// ---------------- scratch ----------------
__device__ float g_ig[(size_t)TT * G3 * BB];   // [t][gate_col j][b], bias folded in
__device__ float g_h[2][HH * BB];              // h[k][b], double buffered
__device__ unsigned g_flags[GRID_R];

// ---------------- helpers ----------------
__device__ __forceinline__ unsigned long long fma2(unsigned long long a,
                                                   unsigned long long b,
                                                   unsigned long long c) {
    unsigned long long d;
    asm("fma.rn.f32x2 %0, %1, %2, %3;" : "=l"(d) : "l"(a), "l"(b), "l"(c));
    return d;
}
__device__ __forceinline__ float2 u2f2(unsigned long long v) {
    float2 f;
    f.x = __uint_as_float((unsigned)(v & 0xffffffffull));
    f.y = __uint_as_float((unsigned)(v >> 32));
    return f;
}
__device__ __forceinline__ float sigmoidf_(float x) {
    return 1.0f / (1.0f + expf(-x));
}
__device__ __forceinline__ void cp16(unsigned dst, const void* src) {
    asm volatile("cp.async.cg.shared.global [%0], [%1], 16;" :: "r"(dst), "l"(src));
}

// ---------------- reset ----------------
__global__ void reset_kernel() {
    int idx = blockIdx.x * blockDim.x + threadIdx.x;
    if (idx < GRID_R) g_flags[idx] = 0;
    for (int i = idx; i < HH * BB; i += gridDim.x * blockDim.x)
        g_h[0][i] = 0.0f;
}

// ---------------- phase 1: IG[t][j][b] = bias[j] + sum_i w_ih[j][i] * xs[b][t][i] ----------------
__global__ void ig_kernel(const float* __restrict__ xs,
                          const float* __restrict__ w_ih,
                          const float* __restrict__ bias) {
    __shared__ float Ws[64][128];
    __shared__ float Xs[64][64];

    const int t   = blockIdx.x;
    const int jb  = blockIdx.y * 128;
    const int tid = threadIdx.x;
    const int tx  = tid & 15;
    const int ty  = tid >> 4;

    float acc[8][4];
#pragma unroll
    for (int i = 0; i < 8; i++)
#pragma unroll
        for (int j = 0; j < 4; j++) acc[i][j] = 0.0f;

    for (int kc = 0; kc < II; kc += 64) {
        {
            int jj = tid >> 1, half = tid & 1;
            const float* src = w_ih + (size_t)(jb + jj) * II + kc + half * 32;
#pragma unroll
            for (int q = 0; q < 8; q++) {
                float4 v = *(const float4*)(src + q * 4);
                int ik = half * 32 + q * 4;
                Ws[ik + 0][jj] = v.x; Ws[ik + 1][jj] = v.y;
                Ws[ik + 2][jj] = v.z; Ws[ik + 3][jj] = v.w;
            }
        }
        {
            int b = tid >> 2, q = tid & 3;
            const float* src = xs + ((size_t)b * TT + t) * II + kc + q * 16;
#pragma unroll
            for (int v = 0; v < 4; v++) {
                float4 x4 = *(const float4*)(src + v * 4);
                int ik = q * 16 + v * 4;
                Xs[ik + 0][b] = x4.x; Xs[ik + 1][b] = x4.y;
                Xs[ik + 2][b] = x4.z; Xs[ik + 3][b] = x4.w;
            }
        }
        __syncthreads();
#pragma unroll
        for (int ik = 0; ik < 64; ik++) {
            float4 a0 = *(const float4*)&Ws[ik][ty * 8];
            float4 a1 = *(const float4*)&Ws[ik][ty * 8 + 4];
            float4 xv = *(const float4*)&Xs[ik][tx * 4];
            float a[8] = {a0.x, a0.y, a0.z, a0.w, a1.x, a1.y, a1.z, a1.w};
            float x[4] = {xv.x, xv.y, xv.z, xv.w};
#pragma unroll
            for (int i = 0; i < 8; i++)
#pragma unroll
                for (int j = 0; j < 4; j++)
                    acc[i][j] = fmaf(a[i], x[j], acc[i][j]);
        }
        __syncthreads();
    }
#pragma unroll
    for (int i = 0; i < 8; i++) {
        int j = jb + ty * 8 + i;
        float bj = bias[j];
        float4 o = {acc[i][0] + bj, acc[i][1] + bj, acc[i][2] + bj, acc[i][3] + bj};
        *(float4*)&g_ig[((size_t)t * G3 + j) * BB + tx * 4] = o;
    }
}

// ---------------- phase 2: persistent recurrence ----------------
__global__ void __launch_bounds__(BLK_R, 1)
gru_kernel(const float* __restrict__ w_hh,
           const float* __restrict__ b_n_p,
           float* __restrict__ out) {
    extern __shared__ __align__(16) float smf[];
    float*  sh_h  = smf + SMEM_F_H;                 // [512][64]
    float2* sw2   = (float2*)(smf + SMEM_F_W);      // [8][12][64] dup pairs (local k)
    float*  sh_pt = smf + SMEM_F_P;                 // [8][12][64]

    const int tid  = threadIdx.x;
    const int warp = tid >> 5;
    const int lane = tid & 31;
    const int b0   = lane * 2;
    const int jp4  = blockIdx.x * 4;                // 4 hidden columns per CTA

    unsigned sh_h_addr;
    asm("{ .reg .u64 t0; cvta.to.shared.u64 t0, %1; cvt.u32.u64 %0, t0; }"
        : "=r"(sh_h_addr) : "l"(sh_h));

    // stage weights once: sw2[w][gc][kl] = dup(w_hh[(g*H + jp4+jj)*H + w*64+kl]), gc=g*4+jj
    for (int idx = tid; idx < 8 * 12 * 64; idx += BLK_R) {
        int w   = idx / 768;
        int rem = idx - w * 768;
        int gc  = rem >> 6;
        int kl  = rem & 63;
        int g   = gc >> 2, jj = gc & 3;
        float v = w_hh[(size_t)(g * HH + jp4 + jj) * HH + w * 64 + kl];
        sw2[(w * 12 + gc) * 64 + kl] = make_float2(v, v);
    }

    // per-thread output assignment: one (jj, b) per thread (256 = 4*64)
    const int jj = tid >> 6;
    const int b  = tid & 63;
    const int jg = jp4 + jj;
    const float bn = b_n_p[jg];
    __syncthreads();

    // preload ig for t=0
    float igr, igz, ign;
    {
        const float* p = g_ig;
        igr = p[(size_t)(0 * HH + jg) * BB + b];
        igz = p[(size_t)(1 * HH + jg) * BB + b];
        ign = p[(size_t)(2 * HH + jg) * BB + b];
    }

    for (int t = 0; t < TT; t++) {
        const float* hcur  = g_h[t & 1];
        float*       hnext = g_h[(t + 1) & 1];

        // stage this warp's 16 KB k-chunk in 2 sub-chunks of 8 KB
        {
            const float4* src = (const float4*)hcur;
#pragma unroll
            for (int s = 0; s < 2; s++) {
                int base4 = (warp * 64 + s * 32) * 16;   // float4 index
#pragma unroll
                for (int i = 0; i < 16; i++) {
                    int idx = base4 + i * 32 + lane;
                    cp16(sh_h_addr + idx * 16, src + idx);
                }
                asm volatile("cp.async.commit_group;");
            }
        }

        // prefetch ig for t+1 (DRAM latency overlaps compute + barrier)
        float nigr = 0.0f, nigz = 0.0f, nign = 0.0f;
        if (t + 1 < TT) {
            const float* p = g_ig + (size_t)(t + 1) * G3 * BB;
            nigr = p[(size_t)(0 * HH + jg) * BB + b];
            nigz = p[(size_t)(1 * HH + jg) * BB + b];
            nign = p[(size_t)(2 * HH + jg) * BB + b];
        }

        unsigned long long acc[12];
#pragma unroll
        for (int gc = 0; gc < 12; gc++) acc[gc] = 0ull;

#pragma unroll 1
        for (int s = 0; s < 2; s++) {
            if (s == 0) asm volatile("cp.async.wait_group 1;");
            else        asm volatile("cp.async.wait_group 0;");
            const int kb = warp * 64 + s * 32;
#pragma unroll 4
            for (int kk = 0; kk < 32; kk += 2) {
                const int k  = kb + kk;        // global k (h rows)
                const int kl = s * 32 + kk;    // local k (this warp's weight region)
                const unsigned long long* hrow = (const unsigned long long*)sh_h;
                unsigned long long h0 = hrow[(k + 0) * 32 + lane];
                unsigned long long h1 = hrow[(k + 1) * 32 + lane];
#pragma unroll
                for (int gc = 0; gc < 12; gc++) {
                    ulonglong2 w2 = *(const ulonglong2*)&sw2[(warp * 12 + gc) * 64 + kl];
                    acc[gc] = fma2(h0, w2.x, acc[gc]);
                    acc[gc] = fma2(h1, w2.y, acc[gc]);
                }
            }
        }

        // publish partials
#pragma unroll
        for (int gc = 0; gc < 12; gc++)
            *(float2*)&sh_pt[(warp * 12 + gc) * 64 + b0] = u2f2(acc[gc]);
        __syncthreads();   // (A)

        // reduce + gates + h write (one (jj,b) per thread)
        {
            float pr = 0.0f, pz = 0.0f, pn = 0.0f;
#pragma unroll
            for (int w = 0; w < 8; w++) {
                pr += sh_pt[(w * 12 + 0 * 4 + jj) * 64 + b];
                pz += sh_pt[(w * 12 + 1 * 4 + jj) * 64 + b];
                pn += sh_pt[(w * 12 + 2 * 4 + jj) * 64 + b];
            }
            float r    = sigmoidf_(igr + pr);
            float z    = sigmoidf_(igz + pz);
            float hold = sh_h[jg * 64 + b];
            float n    = tanhf(ign + r * (pn + bn));
            float hnew = n + z * (hold - n);
            if (t == TT - 1) out[b * HH + jg] = hnew;
            else             hnext[jg * 64 + b] = hnew;
        }
        igr = nigr; igz = nigz; ign = nign;
        __syncthreads();   // (B) all h writes + smem reads done

        if (t < TT - 1) {
            if (tid == 0)
                asm volatile("st.release.gpu.u32 [%0], %1;"
                             :: "l"(g_flags + blockIdx.x), "r"(t + 1) : "memory");
            if (tid < GRID_R) {
                unsigned v;
                do {
                    asm volatile("ld.acquire.gpu.u32 %0, [%1];"
                                 : "=r"(v) : "l"(g_flags + tid) : "memory");
                } while (v < (unsigned)(t + 1));
            }
            __syncthreads();   // (C) whole CTA gated on all 128 flags
        }
    }
}

// ---------------- launch ----------------
extern "C" void kernel_launch(void* const* d_in, const int* in_sizes, int n_in,
                              void* d_out, int out_size) {
    const float* xs   = (const float*)d_in[0];
    const float* w_ih = (const float*)d_in[1];
    const float* w_hh = (const float*)d_in[2];
    const float* bias = (const float*)d_in[3];
    const float* b_n  = (const float*)d_in[4];
    float* out = (float*)d_out;

    cudaFuncSetAttribute(gru_kernel,
                         cudaFuncAttributeMaxDynamicSharedMemorySize, SMEM_BYTES);

    reset_kernel<<<64, 256>>>();

    dim3 g1(TT, G3 / 128);
    ig_kernel<<<g1, 256>>>(xs, w_ih, bias);

    gru_kernel<<<GRID_R, BLK_R, SMEM_BYTES>>>(w_hh, b_n, out);
}

// round 9
// speedup vs baseline: 2.4095x; 1.4643x over previous
#include <cuda_runtime.h>
#include <math.h>

#define BB 64
#define TT 2048
#define II 256
#define HH 512
#define G3 1536          // 3*H

// recurrent grid: 16 j-CTAs x 8 b-groups = 128 CTAs (co-resident)
#define NJ 16            // j-blocks (32 j each)
#define NB 8             // b-groups (8 b each)
#define BLK_R 256        // 8 warps

// smem (floats): W 49152 | H 8192 (partials 1536 aliased at H start)
#define SM_W 0
#define SM_H 49152
#define SMEM_FLOATS (49152 + 8192)
#define SMEM_BYTES  (SMEM_FLOATS * 4)   // 229376 <= 232448

// ---------------- scratch ----------------
__device__ float g_ig[(size_t)TT * G3 * BB];     // [t][j 0..1535][b 0..63]
__device__ float g_hx[NB][2][256][8][4];         // per group: [buf][kp][b][dup4]
__device__ unsigned g_flags2[NB * NJ * 64];      // 256-B padded flags

// ---------------- helpers ----------------
__device__ __forceinline__ unsigned long long fma2(unsigned long long a,
                                                   unsigned long long b,
                                                   unsigned long long c) {
    unsigned long long d;
    asm("fma.rn.f32x2 %0, %1, %2, %3;" : "=l"(d) : "l"(a), "l"(b), "l"(c));
    return d;
}
__device__ __forceinline__ float2 u2f2(unsigned long long v) {
    float2 f;
    f.x = __uint_as_float((unsigned)(v & 0xffffffffull));
    f.y = __uint_as_float((unsigned)(v >> 32));
    return f;
}
__device__ __forceinline__ float sigmoidf_(float x) {
    return 1.0f / (1.0f + expf(-x));
}
__device__ __forceinline__ void cp16(unsigned dst, const void* src) {
    asm volatile("cp.async.cg.shared.global [%0], [%1], 16;" :: "r"(dst), "l"(src));
}

// ---------------- reset ----------------
__global__ void reset_kernel() {
    int idx = blockIdx.x * blockDim.x + threadIdx.x;
    if (idx < NB * NJ) g_flags2[idx * 64] = 0;
}

// ---------------- phase 1: IG[t][j][b] = bias[j] + sum_i w_ih[j][i] * xs[b][t][i] ----------------
__global__ void ig_kernel(const float* __restrict__ xs,
                          const float* __restrict__ w_ih,
                          const float* __restrict__ bias) {
    __shared__ float Ws[64][128];
    __shared__ float Xs[64][64];

    const int t   = blockIdx.x;
    const int jb  = blockIdx.y * 128;
    const int tid = threadIdx.x;
    const int tx  = tid & 15;
    const int ty  = tid >> 4;

    float acc[8][4];
#pragma unroll
    for (int i = 0; i < 8; i++)
#pragma unroll
        for (int j = 0; j < 4; j++) acc[i][j] = 0.0f;

    for (int kc = 0; kc < II; kc += 64) {
        {
            int jj = tid >> 1, half = tid & 1;
            const float* src = w_ih + (size_t)(jb + jj) * II + kc + half * 32;
#pragma unroll
            for (int q = 0; q < 8; q++) {
                float4 v = *(const float4*)(src + q * 4);
                int ik = half * 32 + q * 4;
                Ws[ik + 0][jj] = v.x; Ws[ik + 1][jj] = v.y;
                Ws[ik + 2][jj] = v.z; Ws[ik + 3][jj] = v.w;
            }
        }
        {
            int b = tid >> 2, q = tid & 3;
            const float* src = xs + ((size_t)b * TT + t) * II + kc + q * 16;
#pragma unroll
            for (int v = 0; v < 4; v++) {
                float4 x4 = *(const float4*)(src + v * 4);
                int ik = q * 16 + v * 4;
                Xs[ik + 0][b] = x4.x; Xs[ik + 1][b] = x4.y;
                Xs[ik + 2][b] = x4.z; Xs[ik + 3][b] = x4.w;
            }
        }
        __syncthreads();
#pragma unroll
        for (int ik = 0; ik < 64; ik++) {
            float4 a0 = *(const float4*)&Ws[ik][ty * 8];
            float4 a1 = *(const float4*)&Ws[ik][ty * 8 + 4];
            float4 xv = *(const float4*)&Xs[ik][tx * 4];
            float a[8] = {a0.x, a0.y, a0.z, a0.w, a1.x, a1.y, a1.z, a1.w};
            float x[4] = {xv.x, xv.y, xv.z, xv.w};
#pragma unroll
            for (int i = 0; i < 8; i++)
#pragma unroll
                for (int j = 0; j < 4; j++)
                    acc[i][j] = fmaf(a[i], x[j], acc[i][j]);
        }
        __syncthreads();
    }
#pragma unroll
    for (int i = 0; i < 8; i++) {
        int j = jb + ty * 8 + i;
        float bj = bias[j];
        float4 o = {acc[i][0] + bj, acc[i][1] + bj, acc[i][2] + bj, acc[i][3] + bj};
        *(float4*)&g_ig[((size_t)t * G3 + j) * BB + tx * 4] = o;
    }
}

// ---------------- phase 2: persistent recurrence, (j-block, b-group) partition ----------------
__global__ void __launch_bounds__(BLK_R, 1)
gru_kernel(const float* __restrict__ w_hh,
           const float* __restrict__ b_n_p,
           float* __restrict__ out) {
    extern __shared__ __align__(16) float smf[];
    float* smW = smf + SM_W;     // w4[(g*256+kp)*16+jp][4] = (w[j0,2kp],w[j1,2kp],w[j0,2kp+1],w[j1,2kp+1])
    float* smH = smf + SM_H;     // h4[kp][b][4] = (h[2kp],h[2kp],h[2kp+1],h[2kp+1])
    float* smP = smf + SM_H;     // partials alias: [kh][jp][b][g] float2 (1536 floats)

    const int tid = threadIdx.x;
    const int jb  = blockIdx.x & (NJ - 1);   // j-block 0..15
    const int bg  = blockIdx.x >> 4;         // b-group 0..7

    // inner-loop mapping
    const int b_i  = tid & 7;
    const int jp_i = (tid >> 3) & 15;
    const int kh   = tid >> 7;               // k half: 0 or 1
    // gate mapping
    const int jl = tid >> 3;                 // 0..31
    const int bG = bg * 8 + b_i;
    const int jG = jb * 32 + jl;
    const float bn = b_n_p[jG];

    unsigned smH_addr;
    asm("{ .reg .u64 t0; cvta.to.shared.u64 t0, %1; cvt.u32.u64 %0, t0; }"
        : "=r"(smH_addr) : "l"(smH));

    // ---- stage weights once (196.6 KB) ----
    for (int idx = tid; idx < 3 * 256 * 16 * 4; idx += BLK_R) {
        int e  = idx & 3;
        int jp = (idx >> 2) & 15;
        int kp = (idx >> 6) & 255;
        int g  = idx >> 14;
        int j  = jb * 32 + 2 * jp + (e & 1);
        int k  = 2 * kp + (e >> 1);
        smW[idx] = w_hh[(size_t)(g * HH + j) * HH + k];
    }
    // ---- h0 = 0 in smem (dup layout) ----
    for (int idx = tid; idx < 8192; idx += BLK_R) smH[idx] = 0.0f;

    float hreg = 0.0f;   // this thread's (jG, bG) hidden value

    // preload ig for t=0
    float igr, igz, ign;
    igr = g_ig[((size_t)0 * G3 + 0 * HH + jG) * BB + bG];
    igz = g_ig[((size_t)0 * G3 + 1 * HH + jG) * BB + bG];
    ign = g_ig[((size_t)0 * G3 + 2 * HH + jG) * BB + bG];
    __syncthreads();

    // per-thread smem bases for inner loop
    // H row (per kp): 8 b * 16 B = 128 B = 8 ulonglong2
    // W row (per kp): 16 jp * 16 B = 256 B = 16 ulonglong2
    const ulonglong2* Hb = (const ulonglong2*)(smH + (size_t)(kh * 128) * 32 + b_i * 4);
    const ulonglong2* W0 = (const ulonglong2*)(smW + ((0 * 256 + kh * 128) * 16 + jp_i) * 4);
    const ulonglong2* W1 = (const ulonglong2*)(smW + ((1 * 256 + kh * 128) * 16 + jp_i) * 4);
    const ulonglong2* W2 = (const ulonglong2*)(smW + ((2 * 256 + kh * 128) * 16 + jp_i) * 4);

    for (int t = 0; t < TT; t++) {
        // prefetch ig for t+1
        float nigr = 0.0f, nigz = 0.0f, nign = 0.0f;
        if (t + 1 < TT) {
            const float* p = g_ig + (size_t)(t + 1) * G3 * BB;
            nigr = p[(size_t)(0 * HH + jG) * BB + bG];
            nigz = p[(size_t)(1 * HH + jG) * BB + bG];
            nign = p[(size_t)(2 * HH + jG) * BB + bG];
        }

        // ---- inner dot: 128 k-pairs, dual accumulator sets ----
        unsigned long long aR0 = 0, aR1 = 0, aZ0 = 0, aZ1 = 0, aN0 = 0, aN1 = 0;
#pragma unroll 4
        for (int kp = 0; kp < 128; kp += 2) {
            ulonglong2 h0 = Hb[(kp + 0) * 8];
            ulonglong2 h1 = Hb[(kp + 1) * 8];
            ulonglong2 r0 = W0[(kp + 0) * 16];
            ulonglong2 r1 = W0[(kp + 1) * 16];
            ulonglong2 z0 = W1[(kp + 0) * 16];
            ulonglong2 z1 = W1[(kp + 1) * 16];
            ulonglong2 n0 = W2[(kp + 0) * 16];
            ulonglong2 n1 = W2[(kp + 1) * 16];
            aR0 = fma2(h0.x, r0.x, aR0);  aR0 = fma2(h0.y, r0.y, aR0);
            aZ0 = fma2(h0.x, z0.x, aZ0);  aZ0 = fma2(h0.y, z0.y, aZ0);
            aN0 = fma2(h0.x, n0.x, aN0);  aN0 = fma2(h0.y, n0.y, aN0);
            aR1 = fma2(h1.x, r1.x, aR1);  aR1 = fma2(h1.y, r1.y, aR1);
            aZ1 = fma2(h1.x, z1.x, aZ1);  aZ1 = fma2(h1.y, z1.y, aZ1);
            aN1 = fma2(h1.x, n1.x, aN1);  aN1 = fma2(h1.y, n1.y, aN1);
        }
        float2 fR = u2f2(aR0), fZ = u2f2(aZ0), fN = u2f2(aN0);
        float2 gR = u2f2(aR1), gZ = u2f2(aZ1), gN = u2f2(aN1);
        fR.x += gR.x; fR.y += gR.y;
        fZ.x += gZ.x; fZ.y += gZ.y;
        fN.x += gN.x; fN.y += gN.y;

        __syncthreads();   // all inner reads of smH done (partials alias smH)

        // publish partials: [kh][jp][b][g] float2
        {
            float2* P = (float2*)smP;
            int base = ((kh * 16 + jp_i) * 8 + b_i) * 3;
            P[base + 0] = fR;
            P[base + 1] = fZ;
            P[base + 2] = fN;
        }
        __syncthreads();

        // ---- gates: one (jl, b) per thread ----
        float hnew;
        {
            const float2* P = (const float2*)smP;
            int jp = jl >> 1, c = jl & 1;
            int i0 = ((0 * 16 + jp) * 8 + b_i) * 3;
            int i1 = ((1 * 16 + jp) * 8 + b_i) * 3;
            float pr = (c ? P[i0 + 0].y : P[i0 + 0].x) + (c ? P[i1 + 0].y : P[i1 + 0].x);
            float pz = (c ? P[i0 + 1].y : P[i0 + 1].x) + (c ? P[i1 + 1].y : P[i1 + 1].x);
            float pn = (c ? P[i0 + 2].y : P[i0 + 2].x) + (c ? P[i1 + 2].y : P[i1 + 2].x);
            float r = sigmoidf_(igr + pr);
            float z = sigmoidf_(igz + pz);
            float n = tanhf(ign + r * (pn + bn));
            hnew = n + z * (hreg - n);
            hreg = hnew;
        }
        igr = nigr; igz = nigz; ign = nign;

        if (t == TT - 1) {
            out[(size_t)bG * HH + jG] = hnew;
        } else {
            const int nxt = (t + 1) & 1;
            // write dup pair to group h buffer
            *(float2*)&g_hx[bg][nxt][jG >> 1][b_i][2 * (jG & 1)] = make_float2(hnew, hnew);
            __syncthreads();   // all STGs issued before release

            // group barrier (16 CTAs)
            if (tid == 0)
                asm volatile("st.release.gpu.u32 [%0], %1;"
                             :: "l"(g_flags2 + (size_t)(bg * NJ + jb) * 64), "r"(t + 1) : "memory");
            if (tid < NJ) {
                unsigned v;
                do {
                    asm volatile("ld.acquire.gpu.u32 %0, [%1];"
                                 : "=r"(v) : "l"(g_flags2 + (size_t)(bg * NJ + tid) * 64) : "memory");
                } while (v < (unsigned)(t + 1));
            }
            __syncthreads();

            // pull h(t+1) into smem (32 KB, L2-resident)
            {
                const float4* src = (const float4*)&g_hx[bg][nxt][0][0][0];
#pragma unroll
                for (int i = 0; i < 8; i++) {
                    int idx = tid + i * BLK_R;
                    cp16(smH_addr + idx * 16, src + idx);
                }
                asm volatile("cp.async.commit_group;");
                asm volatile("cp.async.wait_group 0;");
            }
            __syncthreads();
        }
    }
}

// ---------------- launch ----------------
extern "C" void kernel_launch(void* const* d_in, const int* in_sizes, int n_in,
                              void* d_out, int out_size) {
    const float* xs   = (const float*)d_in[0];
    const float* w_ih = (const float*)d_in[1];
    const float* w_hh = (const float*)d_in[2];
    const float* bias = (const float*)d_in[3];
    const float* b_n  = (const float*)d_in[4];
    float* out = (float*)d_out;

    cudaFuncSetAttribute(gru_kernel,
                         cudaFuncAttributeMaxDynamicSharedMemorySize, SMEM_BYTES);

    reset_kernel<<<1, 128>>>();

    dim3 g1(TT, G3 / 128);
    ig_kernel<<<g1, 256>>>(xs, w_ih, bias);

    gru_kernel<<<NJ * NB, BLK_R, SMEM_BYTES>>>(w_hh, b_n, out);
}

// round 11
// speedup vs baseline: 3.1741x; 1.3173x over previous
#include <cuda_runtime.h>
#include <math.h>

#define BB 64
#define TT 2048
#define II 256
#define HH 512
#define G3 1536          // 3*H

// recurrent grid: 16 j-CTAs x 8 b-groups = 128 CTAs (co-resident)
#define NJ 16            // j-blocks (32 j each)
#define NB 8             // b-groups (8 b each)
#define BLK_R 256        // 8 warps; warp = k-eighth (32 kp each)

// smem (floats): W 49152 | H 8192 (partials 6144 aliased at H start)
#define SM_W 0
#define SM_H 49152
#define SMEM_FLOATS (49152 + 8192)
#define SMEM_BYTES  (SMEM_FLOATS * 4)   // 229376 <= 232448

// ---------------- scratch ----------------
__device__ float g_ig[(size_t)TT * G3 * BB];     // [t][j 0..1535][b 0..63]
__device__ float g_hx[NB][2][256][8][4];         // per group: [buf][kp][b][dup4]
__device__ unsigned g_flags2[NB * NJ * 64];      // 256-B padded flags

// ---------------- helpers ----------------
__device__ __forceinline__ unsigned long long fma2(unsigned long long a,
                                                   unsigned long long b,
                                                   unsigned long long c) {
    unsigned long long d;
    asm("fma.rn.f32x2 %0, %1, %2, %3;" : "=l"(d) : "l"(a), "l"(b), "l"(c));
    return d;
}
__device__ __forceinline__ float2 u2f2(unsigned long long v) {
    float2 f;
    f.x = __uint_as_float((unsigned)(v & 0xffffffffull));
    f.y = __uint_as_float((unsigned)(v >> 32));
    return f;
}
__device__ __forceinline__ float sigmoidf_(float x) {
    return 1.0f / (1.0f + expf(-x));
}
__device__ __forceinline__ void cp16(unsigned dst, const void* src) {
    asm volatile("cp.async.cg.shared.global [%0], [%1], 16;" :: "r"(dst), "l"(src));
}

// ---------------- reset ----------------
__global__ void reset_kernel() {
    int idx = blockIdx.x * blockDim.x + threadIdx.x;
    if (idx < NB * NJ) g_flags2[idx * 64] = 0;
}

// ---------------- phase 1: IG[t][j][b] = bias[j] + sum_i w_ih[j][i] * xs[b][t][i] ----------------
__global__ void ig_kernel(const float* __restrict__ xs,
                          const float* __restrict__ w_ih,
                          const float* __restrict__ bias) {
    __shared__ float Ws[64][128];
    __shared__ float Xs[64][64];

    const int t   = blockIdx.x;
    const int jb  = blockIdx.y * 128;
    const int tid = threadIdx.x;
    const int tx  = tid & 15;
    const int ty  = tid >> 4;

    float acc[8][4];
#pragma unroll
    for (int i = 0; i < 8; i++)
#pragma unroll
        for (int j = 0; j < 4; j++) acc[i][j] = 0.0f;

    for (int kc = 0; kc < II; kc += 64) {
        {
            int jj = tid >> 1, half = tid & 1;
            const float* src = w_ih + (size_t)(jb + jj) * II + kc + half * 32;
#pragma unroll
            for (int q = 0; q < 8; q++) {
                float4 v = *(const float4*)(src + q * 4);
                int ik = half * 32 + q * 4;
                Ws[ik + 0][jj] = v.x; Ws[ik + 1][jj] = v.y;
                Ws[ik + 2][jj] = v.z; Ws[ik + 3][jj] = v.w;
            }
        }
        {
            int b = tid >> 2, q = tid & 3;
            const float* src = xs + ((size_t)b * TT + t) * II + kc + q * 16;
#pragma unroll
            for (int v = 0; v < 4; v++) {
                float4 x4 = *(const float4*)(src + v * 4);
                int ik = q * 16 + v * 4;
                Xs[ik + 0][b] = x4.x; Xs[ik + 1][b] = x4.y;
                Xs[ik + 2][b] = x4.z; Xs[ik + 3][b] = x4.w;
            }
        }
        __syncthreads();
#pragma unroll
        for (int ik = 0; ik < 64; ik++) {
            float4 a0 = *(const float4*)&Ws[ik][ty * 8];
            float4 a1 = *(const float4*)&Ws[ik][ty * 8 + 4];
            float4 xv = *(const float4*)&Xs[ik][tx * 4];
            float a[8] = {a0.x, a0.y, a0.z, a0.w, a1.x, a1.y, a1.z, a1.w};
            float x[4] = {xv.x, xv.y, xv.z, xv.w};
#pragma unroll
            for (int i = 0; i < 8; i++)
#pragma unroll
                for (int j = 0; j < 4; j++)
                    acc[i][j] = fmaf(a[i], x[j], acc[i][j]);
        }
        __syncthreads();
    }
#pragma unroll
    for (int i = 0; i < 8; i++) {
        int j = jb + ty * 8 + i;
        float bj = bias[j];
        float4 o = {acc[i][0] + bj, acc[i][1] + bj, acc[i][2] + bj, acc[i][3] + bj};
        *(float4*)&g_ig[((size_t)t * G3 + j) * BB + tx * 4] = o;
    }
}

// ---------------- phase 2: persistent recurrence, (j-block, b-group) partition ----------------
// Inner mapping: thread = (jp 0..15, bq 0..1, warp = k-eighth). Per kp: 3 W LDS + 4 H LDS
// feed 24 FFMA2 (2 j x 4 b x 3 gates). W amortized over the 4 b in registers.
__global__ void __launch_bounds__(BLK_R, 1)
gru_kernel(const float* __restrict__ w_hh,
           const float* __restrict__ b_n_p,
           float* __restrict__ out) {
    extern __shared__ __align__(16) float smf[];
    float* smW = smf + SM_W;     // w4[(g*256+kp)*16+jp][4] = (w[j0,2kp],w[j1,2kp],w[j0,2kp+1],w[j1,2kp+1])
    float* smH = smf + SM_H;     // h4[kp][b][4] = (h[2kp],h[2kp],h[2kp+1],h[2kp+1])
    float* smP = smf + SM_H;     // partials alias: [(kh*16+jp)*2+bq][iq][g] float2 (6144 floats)

    const int tid = threadIdx.x;
    const int jb  = blockIdx.x & (NJ - 1);   // j-block 0..15
    const int bg  = blockIdx.x >> 4;         // b-group 0..7

    // inner-loop mapping
    const int bq   = tid & 1;                // b quad: b = bq*4 .. +3
    const int jp_i = (tid >> 1) & 15;        // j pair
    const int warp = tid >> 5;               // k-eighth: kp in [warp*32, warp*32+32)
    const int kp0  = warp * 32;
    // gate mapping
    const int b_i = tid & 7;
    const int jl  = tid >> 3;                // 0..31
    const int bG  = bg * 8 + b_i;
    const int jG  = jb * 32 + jl;
    const float bn = b_n_p[jG];

    unsigned smH_addr;
    asm("{ .reg .u64 t0; cvta.to.shared.u64 t0, %1; cvt.u32.u64 %0, t0; }"
        : "=r"(smH_addr) : "l"(smH));

    // ---- stage weights once (196.6 KB) ----
    for (int idx = tid; idx < 3 * 256 * 16 * 4; idx += BLK_R) {
        int e  = idx & 3;
        int jp = (idx >> 2) & 15;
        int kp = (idx >> 6) & 255;
        int g  = idx >> 14;
        int j  = jb * 32 + 2 * jp + (e & 1);
        int k  = 2 * kp + (e >> 1);
        smW[idx] = w_hh[(size_t)(g * HH + j) * HH + k];
    }
    // ---- h0 = 0 in smem (dup layout) ----
    for (int idx = tid; idx < 8192; idx += BLK_R) smH[idx] = 0.0f;

    float hreg = 0.0f;   // this thread's (jG, bG) hidden value

    // preload ig for t=0
    float igr, igz, ign;
    igr = g_ig[((size_t)0 * G3 + 0 * HH + jG) * BB + bG];
    igz = g_ig[((size_t)0 * G3 + 1 * HH + jG) * BB + bG];
    ign = g_ig[((size_t)0 * G3 + 2 * HH + jG) * BB + bG];
    __syncthreads();

    // per-thread smem bases (ulonglong2 = 16 B units)
    // H element index: kp*8 + b   (row = 8 b x 16 B = 128 B)
    // W element index: (g*256+kp)*16 + jp  (row = 16 jp x 16 B = 256 B)
    const ulonglong2* Hb = (const ulonglong2*)smH + bq * 4;
    const ulonglong2* W0 = (const ulonglong2*)smW + 0 * 4096 + jp_i;
    const ulonglong2* W1 = (const ulonglong2*)smW + 1 * 4096 + jp_i;
    const ulonglong2* W2 = (const ulonglong2*)smW + 2 * 4096 + jp_i;

    for (int t = 0; t < TT; t++) {
        // prefetch ig for t+1 (DRAM latency overlaps compute + barrier)
        float nigr = 0.0f, nigz = 0.0f, nign = 0.0f;
        if (t + 1 < TT) {
            const float* p = g_ig + (size_t)(t + 1) * G3 * BB;
            nigr = p[(size_t)(0 * HH + jG) * BB + bG];
            nigz = p[(size_t)(1 * HH + jG) * BB + bG];
            nign = p[(size_t)(2 * HH + jG) * BB + bG];
        }

        // ---- inner dot: 32 kp, 12 accumulators (4 b x 3 gates), j-pair packed ----
        unsigned long long aR0 = 0, aR1 = 0, aR2 = 0, aR3 = 0;
        unsigned long long aZ0 = 0, aZ1 = 0, aZ2 = 0, aZ3 = 0;
        unsigned long long aN0 = 0, aN1 = 0, aN2 = 0, aN3 = 0;
#pragma unroll 4
        for (int kk = 0; kk < 32; kk++) {
            const int kp = kp0 + kk;
            ulonglong2 h0 = Hb[kp * 8 + 0];
            ulonglong2 h1 = Hb[kp * 8 + 1];
            ulonglong2 h2 = Hb[kp * 8 + 2];
            ulonglong2 h3 = Hb[kp * 8 + 3];
            ulonglong2 wr = W0[kp * 16];
            ulonglong2 wz = W1[kp * 16];
            ulonglong2 wn = W2[kp * 16];
            // k = 2kp (x half): 12 independent FFMA2
            aR0 = fma2(h0.x, wr.x, aR0);
            aR1 = fma2(h1.x, wr.x, aR1);
            aR2 = fma2(h2.x, wr.x, aR2);
            aR3 = fma2(h3.x, wr.x, aR3);
            aZ0 = fma2(h0.x, wz.x, aZ0);
            aZ1 = fma2(h1.x, wz.x, aZ1);
            aZ2 = fma2(h2.x, wz.x, aZ2);
            aZ3 = fma2(h3.x, wz.x, aZ3);
            aN0 = fma2(h0.x, wn.x, aN0);
            aN1 = fma2(h1.x, wn.x, aN1);
            aN2 = fma2(h2.x, wn.x, aN2);
            aN3 = fma2(h3.x, wn.x, aN3);
            // k = 2kp+1 (y half)
            aR0 = fma2(h0.y, wr.y, aR0);
            aR1 = fma2(h1.y, wr.y, aR1);
            aR2 = fma2(h2.y, wr.y, aR2);
            aR3 = fma2(h3.y, wr.y, aR3);
            aZ0 = fma2(h0.y, wz.y, aZ0);
            aZ1 = fma2(h1.y, wz.y, aZ1);
            aZ2 = fma2(h2.y, wz.y, aZ2);
            aZ3 = fma2(h3.y, wz.y, aZ3);
            aN0 = fma2(h0.y, wn.y, aN0);
            aN1 = fma2(h1.y, wn.y, aN1);
            aN2 = fma2(h2.y, wn.y, aN2);
            aN3 = fma2(h3.y, wn.y, aN3);
        }

        __syncthreads();   // all inner reads of smH done (partials alias smH)

        // publish partials: P[((warp*16+jp)*2+bq)*4 + iq][g] float2
        {
            float2* P = (float2*)smP;
            int base = (((warp * 16 + jp_i) * 2 + bq) * 4) * 3;
            P[base + 0]  = u2f2(aR0);
            P[base + 1]  = u2f2(aZ0);
            P[base + 2]  = u2f2(aN0);
            P[base + 3]  = u2f2(aR1);
            P[base + 4]  = u2f2(aZ1);
            P[base + 5]  = u2f2(aN1);
            P[base + 6]  = u2f2(aR2);
            P[base + 7]  = u2f2(aZ2);
            P[base + 8]  = u2f2(aN2);
            P[base + 9]  = u2f2(aR3);
            P[base + 10] = u2f2(aZ3);
            P[base + 11] = u2f2(aN3);
        }
        __syncthreads();

        // ---- gates: one (jl, b_i) per thread; reduce over 8 k-eighths ----
        float hnew;
        {
            const float2* P = (const float2*)smP;
            const int jp  = jl >> 1;
            const int c   = jl & 1;
            const int bqg = b_i >> 2;
            const int iq  = b_i & 3;
            float pr = 0.0f, pz = 0.0f, pn = 0.0f;
#pragma unroll
            for (int kh = 0; kh < 8; kh++) {
                int base = ((((kh * 16 + jp) * 2 + bqg) * 4 + iq)) * 3;
                float2 vr = P[base + 0];
                float2 vz = P[base + 1];
                float2 vn = P[base + 2];
                pr += c ? vr.y : vr.x;
                pz += c ? vz.y : vz.x;
                pn += c ? vn.y : vn.x;
            }
            float r = sigmoidf_(igr + pr);
            float z = sigmoidf_(igz + pz);
            float n = tanhf(ign + r * (pn + bn));
            hnew = n + z * (hreg - n);
            hreg = hnew;
        }
        igr = nigr; igz = nigz; ign = nign;

        if (t == TT - 1) {
            out[(size_t)bG * HH + jG] = hnew;
        } else {
            const int nxt = (t + 1) & 1;
            // write dup pair to group h buffer
            *(float2*)&g_hx[bg][nxt][jG >> 1][b_i][2 * (jG & 1)] = make_float2(hnew, hnew);
            __syncthreads();   // all STGs issued + all P reads done before smH overwritten

            // group barrier (16 CTAs)
            if (tid == 0)
                asm volatile("st.release.gpu.u32 [%0], %1;"
                             :: "l"(g_flags2 + (size_t)(bg * NJ + jb) * 64), "r"(t + 1) : "memory");
            if (tid < NJ) {
                unsigned v;
                do {
                    asm volatile("ld.acquire.gpu.u32 %0, [%1];"
                                 : "=r"(v) : "l"(g_flags2 + (size_t)(bg * NJ + tid) * 64) : "memory");
                } while (v < (unsigned)(t + 1));
            }
            __syncthreads();

            // pull h(t+1) into smem (32 KB, L2-resident)
            {
                const float4* src = (const float4*)&g_hx[bg][nxt][0][0][0];
#pragma unroll
                for (int i = 0; i < 8; i++) {
                    int idx = tid + i * BLK_R;
                    cp16(smH_addr + idx * 16, src + idx);
                }
                asm volatile("cp.async.commit_group;");
                asm volatile("cp.async.wait_group 0;");
            }
            __syncthreads();
        }
    }
}

// ---------------- launch ----------------
extern "C" void kernel_launch(void* const* d_in, const int* in_sizes, int n_in,
                              void* d_out, int out_size) {
    const float* xs   = (const float*)d_in[0];
    const float* w_ih = (const float*)d_in[1];
    const float* w_hh = (const float*)d_in[2];
    const float* bias = (const float*)d_in[3];
    const float* b_n  = (const float*)d_in[4];
    float* out = (float*)d_out;

    cudaFuncSetAttribute(gru_kernel,
                         cudaFuncAttributeMaxDynamicSharedMemorySize, SMEM_BYTES);

    reset_kernel<<<1, 128>>>();

    dim3 g1(TT, G3 / 128);
    ig_kernel<<<g1, 256>>>(xs, w_ih, bias);

    gru_kernel<<<NJ * NB, BLK_R, SMEM_BYTES>>>(w_hh, b_n, out);
}

// round 13
// speedup vs baseline: 3.2343x; 1.0190x over previous
#include <cuda_runtime.h>
#include <math.h>

#define BB 64
#define TT 2048
#define II 256
#define HH 512
#define G3 1536          // 3*H

// recurrent grid: 16 j-CTAs x 8 b-groups = 128 CTAs (co-resident)
#define NJ 16            // j-blocks (32 j each)
#define NB 8             // b-groups (8 b each)
#define BLK_R 256        // 8 warps; warp = k-eighth (32 kp each)

// gru smem (floats): W 49152 | H 8192 (partials 6144 aliased at H start)
#define SM_W 0
#define SM_H 49152
#define SMEM_FLOATS (49152 + 8192)
#define SMEM_BYTES  (SMEM_FLOATS * 4)   // 229376 <= 232448

// ig tensor kernel smem (floats), padded stride 68 for conflict-free frags
#define WST   68
#define S_WHI 0
#define S_WLO 8704            // 128*68
#define S_XHI 17408
#define S_XLO 21760           // +64*68
#define IGT_SMEMF 26112
#define IGT_SMEMB (IGT_SMEMF * 4)   // 104448

// ---------------- scratch ----------------
__device__ float g_ig[(size_t)TT * G3 * BB];     // [t][j 0..1535][b 0..63]
__device__ float g_hx[NB][2][256][8][4];         // per group: [buf][kp][b][dup4]
__device__ unsigned g_flags2[NB * NJ * 64];      // 256-B padded flags

// ---------------- helpers ----------------
__device__ __forceinline__ unsigned long long fma2(unsigned long long a,
                                                   unsigned long long b,
                                                   unsigned long long c) {
    unsigned long long d;
    asm("fma.rn.f32x2 %0, %1, %2, %3;" : "=l"(d) : "l"(a), "l"(b), "l"(c));
    return d;
}
__device__ __forceinline__ float2 u2f2(unsigned long long v) {
    float2 f;
    f.x = __uint_as_float((unsigned)(v & 0xffffffffull));
    f.y = __uint_as_float((unsigned)(v >> 32));
    return f;
}
__device__ __forceinline__ float sigmoidf_(float x) {
    return 1.0f / (1.0f + expf(-x));
}
__device__ __forceinline__ void cp16(unsigned dst, const void* src) {
    asm volatile("cp.async.cg.shared.global [%0], [%1], 16;" :: "r"(dst), "l"(src));
}
__device__ __forceinline__ unsigned f2tf32(float x) {
    unsigned u;
    asm("cvt.rna.tf32.f32 %0, %1;" : "=r"(u) : "f"(x));
    return u;
}
__device__ __forceinline__ void mma_tf32(float* c, const unsigned* a, const unsigned* b) {
    asm volatile(
        "mma.sync.aligned.m16n8k8.row.col.f32.tf32.tf32.f32 "
        "{%0,%1,%2,%3}, {%4,%5,%6,%7}, {%8,%9}, {%0,%1,%2,%3};"
        : "+f"(c[0]), "+f"(c[1]), "+f"(c[2]), "+f"(c[3])
        : "r"(a[0]), "r"(a[1]), "r"(a[2]), "r"(a[3]), "r"(b[0]), "r"(b[1]));
}

// ---------------- reset ----------------
__global__ void reset_kernel() {
    int idx = blockIdx.x * blockDim.x + threadIdx.x;
    if (idx < NB * NJ) g_flags2[idx * 64] = 0;
}

// ---------------- phase 1: IG via tf32-split tensor cores ----------------
// IG[t][j][b] = bias[j] + sum_i w_ih[j][i] * xs[b][t][i]
// CTA tile 128j x 64b per t; warp = 32j x 32b; K chunks of 64; 3 split-MMAs.
__global__ void __launch_bounds__(256, 2)
ig_tensor_kernel(const float* __restrict__ xs,
                 const float* __restrict__ w_ih,
                 const float* __restrict__ bias) {
    extern __shared__ __align__(16) float sm[];
    float* Whi = sm + S_WHI;   // [128][WST]
    float* Wlo = sm + S_WLO;
    float* Xhi = sm + S_XHI;   // [64][WST]  (k-major, b in columns)
    float* Xlo = sm + S_XLO;

    const int t    = blockIdx.x;
    const int jb   = blockIdx.y * 128;
    const int tid  = threadIdx.x;
    const int warp = tid >> 5;
    const int lane = tid & 31;
    const int wj   = warp >> 1;    // 0..3: j sub-tile of 32
    const int wb   = warp & 1;     // 0..1: b sub-tile of 32
    const int g    = lane >> 2;    // group 0..7
    const int iq   = lane & 3;     // thread-in-group 0..3

    float acc[2][4][4];
#pragma unroll
    for (int mt = 0; mt < 2; mt++)
#pragma unroll
        for (int nt = 0; nt < 4; nt++)
#pragma unroll
            for (int e = 0; e < 4; e++) acc[mt][nt][e] = 0.0f;

    for (int kc = 0; kc < II; kc += 64) {
        // ---- stage W chunk [128][64] -> tf32 hi/lo ----
        {
            int r = tid >> 1, hf = tid & 1;
            const float* src = w_ih + (size_t)(jb + r) * II + kc + hf * 32;
            float* dh = Whi + r * WST + hf * 32;
            float* dl = Wlo + r * WST + hf * 32;
#pragma unroll
            for (int q = 0; q < 8; q++) {
                float4 v = *(const float4*)(src + q * 4);
                float xv[4] = {v.x, v.y, v.z, v.w};
#pragma unroll
                for (int e = 0; e < 4; e++) {
                    unsigned hu = f2tf32(xv[e]);
                    float hif = __uint_as_float(hu);
                    dh[q * 4 + e] = hif;
                    dl[q * 4 + e] = __uint_as_float(f2tf32(xv[e] - hif));
                }
            }
        }
        // ---- stage X chunk transposed: Xsm[k][b] = xs[b][t][kc+k] ----
        {
            int b = tid >> 2, q = tid & 3;
            const float* src = xs + ((size_t)b * TT + t) * II + kc + q * 16;
#pragma unroll
            for (int v = 0; v < 4; v++) {
                float4 x4 = *(const float4*)(src + v * 4);
                float xv[4] = {x4.x, x4.y, x4.z, x4.w};
                int k = q * 16 + v * 4;
#pragma unroll
                for (int e = 0; e < 4; e++) {
                    unsigned hu = f2tf32(xv[e]);
                    float hif = __uint_as_float(hu);
                    Xhi[(k + e) * WST + b] = hif;
                    Xlo[(k + e) * WST + b] = __uint_as_float(f2tf32(xv[e] - hif));
                }
            }
        }
        __syncthreads();

        // ---- 8 k-steps of m16n8k8 ----
#pragma unroll
        for (int ks = 0; ks < 8; ks++) {
            const int k0 = ks * 8;
            unsigned ah[2][4], al[2][4];
#pragma unroll
            for (int mt = 0; mt < 2; mt++) {
                int jr = wj * 32 + mt * 16;
                ah[mt][0] = __float_as_uint(Whi[(jr + g)     * WST + k0 + iq]);
                ah[mt][1] = __float_as_uint(Whi[(jr + g + 8) * WST + k0 + iq]);
                ah[mt][2] = __float_as_uint(Whi[(jr + g)     * WST + k0 + iq + 4]);
                ah[mt][3] = __float_as_uint(Whi[(jr + g + 8) * WST + k0 + iq + 4]);
                al[mt][0] = __float_as_uint(Wlo[(jr + g)     * WST + k0 + iq]);
                al[mt][1] = __float_as_uint(Wlo[(jr + g + 8) * WST + k0 + iq]);
                al[mt][2] = __float_as_uint(Wlo[(jr + g)     * WST + k0 + iq + 4]);
                al[mt][3] = __float_as_uint(Wlo[(jr + g + 8) * WST + k0 + iq + 4]);
            }
            unsigned bh[4][2], bl[4][2];
#pragma unroll
            for (int nt = 0; nt < 4; nt++) {
                int bc = wb * 32 + nt * 8;
                bh[nt][0] = __float_as_uint(Xhi[(k0 + iq)     * WST + bc + g]);
                bh[nt][1] = __float_as_uint(Xhi[(k0 + iq + 4) * WST + bc + g]);
                bl[nt][0] = __float_as_uint(Xlo[(k0 + iq)     * WST + bc + g]);
                bl[nt][1] = __float_as_uint(Xlo[(k0 + iq + 4) * WST + bc + g]);
            }
#pragma unroll
            for (int mt = 0; mt < 2; mt++)
#pragma unroll
                for (int nt = 0; nt < 4; nt++) {
                    mma_tf32(acc[mt][nt], ah[mt], bh[nt]);
                    mma_tf32(acc[mt][nt], ah[mt], bl[nt]);
                    mma_tf32(acc[mt][nt], al[mt], bh[nt]);
                }
        }
        __syncthreads();
    }

    // ---- epilogue: D rows g/g+8, cols 2iq/2iq+1; add bias; write float2 ----
#pragma unroll
    for (int mt = 0; mt < 2; mt++) {
#pragma unroll
        for (int rr = 0; rr < 2; rr++) {
            int j = jb + wj * 32 + mt * 16 + g + rr * 8;
            float bj = bias[j];
#pragma unroll
            for (int nt = 0; nt < 4; nt++) {
                int bc = wb * 32 + nt * 8 + 2 * iq;
                float2 o = make_float2(acc[mt][nt][rr * 2 + 0] + bj,
                                       acc[mt][nt][rr * 2 + 1] + bj);
                *(float2*)&g_ig[((size_t)t * G3 + j) * BB + bc] = o;
            }
        }
    }
}

// ---------------- phase 2: persistent recurrence (unchanged from R11) ----------------
__global__ void __launch_bounds__(BLK_R, 1)
gru_kernel(const float* __restrict__ w_hh,
           const float* __restrict__ b_n_p,
           float* __restrict__ out) {
    extern __shared__ __align__(16) float smf[];
    float* smW = smf + SM_W;
    float* smH = smf + SM_H;
    float* smP = smf + SM_H;

    const int tid = threadIdx.x;
    const int jb  = blockIdx.x & (NJ - 1);
    const int bg  = blockIdx.x >> 4;

    const int bq   = tid & 1;
    const int jp_i = (tid >> 1) & 15;
    const int warp = tid >> 5;
    const int kp0  = warp * 32;
    const int b_i = tid & 7;
    const int jl  = tid >> 3;
    const int bG  = bg * 8 + b_i;
    const int jG  = jb * 32 + jl;
    const float bn = b_n_p[jG];

    unsigned smH_addr;
    asm("{ .reg .u64 t0; cvta.to.shared.u64 t0, %1; cvt.u32.u64 %0, t0; }"
        : "=r"(smH_addr) : "l"(smH));

    for (int idx = tid; idx < 3 * 256 * 16 * 4; idx += BLK_R) {
        int e  = idx & 3;
        int jp = (idx >> 2) & 15;
        int kp = (idx >> 6) & 255;
        int g  = idx >> 14;
        int j  = jb * 32 + 2 * jp + (e & 1);
        int k  = 2 * kp + (e >> 1);
        smW[idx] = w_hh[(size_t)(g * HH + j) * HH + k];
    }
    for (int idx = tid; idx < 8192; idx += BLK_R) smH[idx] = 0.0f;

    float hreg = 0.0f;

    float igr, igz, ign;
    igr = g_ig[((size_t)0 * G3 + 0 * HH + jG) * BB + bG];
    igz = g_ig[((size_t)0 * G3 + 1 * HH + jG) * BB + bG];
    ign = g_ig[((size_t)0 * G3 + 2 * HH + jG) * BB + bG];
    __syncthreads();

    const ulonglong2* Hb = (const ulonglong2*)smH + bq * 4;
    const ulonglong2* W0 = (const ulonglong2*)smW + 0 * 4096 + jp_i;
    const ulonglong2* W1 = (const ulonglong2*)smW + 1 * 4096 + jp_i;
    const ulonglong2* W2 = (const ulonglong2*)smW + 2 * 4096 + jp_i;

    for (int t = 0; t < TT; t++) {
        float nigr = 0.0f, nigz = 0.0f, nign = 0.0f;
        if (t + 1 < TT) {
            const float* p = g_ig + (size_t)(t + 1) * G3 * BB;
            nigr = p[(size_t)(0 * HH + jG) * BB + bG];
            nigz = p[(size_t)(1 * HH + jG) * BB + bG];
            nign = p[(size_t)(2 * HH + jG) * BB + bG];
        }

        unsigned long long aR0 = 0, aR1 = 0, aR2 = 0, aR3 = 0;
        unsigned long long aZ0 = 0, aZ1 = 0, aZ2 = 0, aZ3 = 0;
        unsigned long long aN0 = 0, aN1 = 0, aN2 = 0, aN3 = 0;
#pragma unroll 4
        for (int kk = 0; kk < 32; kk++) {
            const int kp = kp0 + kk;
            ulonglong2 h0 = Hb[kp * 8 + 0];
            ulonglong2 h1 = Hb[kp * 8 + 1];
            ulonglong2 h2 = Hb[kp * 8 + 2];
            ulonglong2 h3 = Hb[kp * 8 + 3];
            ulonglong2 wr = W0[kp * 16];
            ulonglong2 wz = W1[kp * 16];
            ulonglong2 wn = W2[kp * 16];
            aR0 = fma2(h0.x, wr.x, aR0);
            aR1 = fma2(h1.x, wr.x, aR1);
            aR2 = fma2(h2.x, wr.x, aR2);
            aR3 = fma2(h3.x, wr.x, aR3);
            aZ0 = fma2(h0.x, wz.x, aZ0);
            aZ1 = fma2(h1.x, wz.x, aZ1);
            aZ2 = fma2(h2.x, wz.x, aZ2);
            aZ3 = fma2(h3.x, wz.x, aZ3);
            aN0 = fma2(h0.x, wn.x, aN0);
            aN1 = fma2(h1.x, wn.x, aN1);
            aN2 = fma2(h2.x, wn.x, aN2);
            aN3 = fma2(h3.x, wn.x, aN3);
            aR0 = fma2(h0.y, wr.y, aR0);
            aR1 = fma2(h1.y, wr.y, aR1);
            aR2 = fma2(h2.y, wr.y, aR2);
            aR3 = fma2(h3.y, wr.y, aR3);
            aZ0 = fma2(h0.y, wz.y, aZ0);
            aZ1 = fma2(h1.y, wz.y, aZ1);
            aZ2 = fma2(h2.y, wz.y, aZ2);
            aZ3 = fma2(h3.y, wz.y, aZ3);
            aN0 = fma2(h0.y, wn.y, aN0);
            aN1 = fma2(h1.y, wn.y, aN1);
            aN2 = fma2(h2.y, wn.y, aN2);
            aN3 = fma2(h3.y, wn.y, aN3);
        }

        __syncthreads();

        {
            float2* P = (float2*)smP;
            int base = (((warp * 16 + jp_i) * 2 + bq) * 4) * 3;
            P[base + 0]  = u2f2(aR0);
            P[base + 1]  = u2f2(aZ0);
            P[base + 2]  = u2f2(aN0);
            P[base + 3]  = u2f2(aR1);
            P[base + 4]  = u2f2(aZ1);
            P[base + 5]  = u2f2(aN1);
            P[base + 6]  = u2f2(aR2);
            P[base + 7]  = u2f2(aZ2);
            P[base + 8]  = u2f2(aN2);
            P[base + 9]  = u2f2(aR3);
            P[base + 10] = u2f2(aZ3);
            P[base + 11] = u2f2(aN3);
        }
        __syncthreads();

        float hnew;
        {
            const float2* P = (const float2*)smP;
            const int jp  = jl >> 1;
            const int c   = jl & 1;
            const int bqg = b_i >> 2;
            const int iq  = b_i & 3;
            float pr = 0.0f, pz = 0.0f, pn = 0.0f;
#pragma unroll
            for (int kh = 0; kh < 8; kh++) {
                int base = ((((kh * 16 + jp) * 2 + bqg) * 4 + iq)) * 3;
                float2 vr = P[base + 0];
                float2 vz = P[base + 1];
                float2 vn = P[base + 2];
                pr += c ? vr.y : vr.x;
                pz += c ? vz.y : vz.x;
                pn += c ? vn.y : vn.x;
            }
            float r = sigmoidf_(igr + pr);
            float z = sigmoidf_(igz + pz);
            float n = tanhf(ign + r * (pn + bn));
            hnew = n + z * (hreg - n);
            hreg = hnew;
        }
        igr = nigr; igz = nigz; ign = nign;

        if (t == TT - 1) {
            out[(size_t)bG * HH + jG] = hnew;
        } else {
            const int nxt = (t + 1) & 1;
            *(float2*)&g_hx[bg][nxt][jG >> 1][b_i][2 * (jG & 1)] = make_float2(hnew, hnew);
            __syncthreads();

            if (tid == 0)
                asm volatile("st.release.gpu.u32 [%0], %1;"
                             :: "l"(g_flags2 + (size_t)(bg * NJ + jb) * 64), "r"(t + 1) : "memory");
            if (tid < NJ) {
                unsigned v;
                do {
                    asm volatile("ld.acquire.gpu.u32 %0, [%1];"
                                 : "=r"(v) : "l"(g_flags2 + (size_t)(bg * NJ + tid) * 64) : "memory");
                } while (v < (unsigned)(t + 1));
            }
            __syncthreads();

            {
                const float4* src = (const float4*)&g_hx[bg][nxt][0][0][0];
#pragma unroll
                for (int i = 0; i < 8; i++) {
                    int idx = tid + i * BLK_R;
                    cp16(smH_addr + idx * 16, src + idx);
                }
                asm volatile("cp.async.commit_group;");
                asm volatile("cp.async.wait_group 0;");
            }
            __syncthreads();
        }
    }
}

// ---------------- launch ----------------
extern "C" void kernel_launch(void* const* d_in, const int* in_sizes, int n_in,
                              void* d_out, int out_size) {
    const float* xs   = (const float*)d_in[0];
    const float* w_ih = (const float*)d_in[1];
    const float* w_hh = (const float*)d_in[2];
    const float* bias = (const float*)d_in[3];
    const float* b_n  = (const float*)d_in[4];
    float* out = (float*)d_out;

    cudaFuncSetAttribute(gru_kernel,
                         cudaFuncAttributeMaxDynamicSharedMemorySize, SMEM_BYTES);
    cudaFuncSetAttribute(ig_tensor_kernel,
                         cudaFuncAttributeMaxDynamicSharedMemorySize, IGT_SMEMB);

    reset_kernel<<<1, 128>>>();

    dim3 g1(TT, G3 / 128);
    ig_tensor_kernel<<<g1, 256, IGT_SMEMB>>>(xs, w_ih, bias);

    gru_kernel<<<NJ * NB, BLK_R, SMEM_BYTES>>>(w_hh, b_n, out);
}